// round 1
// baseline (speedup 1.0000x reference)
#include <cuda_runtime.h>
#include <cuda_bf16.h>

// ---------------- problem constants ----------------
#define NN 50000              // nodes
#define EE 800000             // edges
#define DD 128                // model dim
#define HH 8                  // heads
#define LL 3                  // layers

static constexpr size_t NF = (size_t)NN * DD;   // 6,400,000 floats per node tensor

// scratch layout (floats) inside one big device array
static constexpr size_t OFF_X   = 0;
static constexpr size_t OFF_Q   = 1 * NF;
static constexpr size_t OFF_K   = 2 * NF;
static constexpr size_t OFF_V   = 3 * NF;
static constexpr size_t OFF_WV  = 4 * NF;
static constexpr size_t OFF_ATT = 5 * NF;
static constexpr size_t OFF_Y   = 6 * NF;
static constexpr size_t OFF_X1  = 7 * NF;
static constexpr size_t OFF_Y2  = 8 * NF;
static constexpr size_t OFF_T   = 9 * NF;           // 50000 x 256
static constexpr size_t OFF_Z   = 11 * NF;          // 50000 x 8
static constexpr size_t OFF_ACC = 11 * NF + 400000; // 128
static constexpr size_t SCRATCH_FLOATS = 11 * NF + 400000 + 128 + 16384; // pad for tile overreads

__device__ float d_scratch[SCRATCH_FLOATS];

// ---------------- packed fp32x2 helpers (Blackwell FFMA2) ----------------
__device__ __forceinline__ unsigned long long pack2(float x, float y) {
    unsigned long long r;
    asm("mov.b64 %0, {%1, %2};" : "=l"(r) : "f"(x), "f"(y));
    return r;
}
__device__ __forceinline__ void unpack2(unsigned long long v, float& x, float& y) {
    asm("mov.b64 {%0, %1}, %2;" : "=f"(x), "=f"(y) : "l"(v));
}
__device__ __forceinline__ void ffma2(unsigned long long& d,
                                      unsigned long long a, unsigned long long b) {
    asm("fma.rn.f32x2 %0, %1, %2, %0;" : "+l"(d) : "l"(a), "l"(b));
}

// ---------------- embedding gather ----------------
__global__ void embed_kernel(const int* __restrict__ idx, const float* __restrict__ emb) {
    int i = blockIdx.x * 256 + threadIdx.x;   // 0 .. NN*DD
    if (i < NN * DD) {
        int n = i >> 7;
        int d = i & 127;
        d_scratch[OFF_X + i] = emb[(size_t)idx[n] * DD + d];
    }
}

// ---------------- zero fill ----------------
__global__ void zero_kernel(size_t off, int n) {
    int i = blockIdx.x * 256 + threadIdx.x;
    if (i < n) d_scratch[off + i] = 0.0f;
}

// ---------------- GEMM: C[M,NOUT] = A[M,K] @ W[K,NOUT] + bias, optional ReLU ----------------
// fp32 with packed f32x2 FMA. BM=64 rows per block, 256 threads.
// Thread (ty,tx): rows ty*4..+3, float-col pairs {2*tx,2*tx+1} + 32*jj.
template<int K, int NOUT, bool RELU>
__launch_bounds__(256)
__global__ void gemm_kernel(size_t aOff, const float* __restrict__ W,
                            const float* __restrict__ bias, size_t cOff, int M)
{
    constexpr int BM = 64, BK = 32;
    constexpr int TM = 4;
    constexpr int TNH = NOUT / 32;     // ull (pair) columns per thread
    __shared__ unsigned long long As2[BK * (BM + 1)];      // duplicated-pair A
    __shared__ __align__(16) float Ws[BK * NOUT];

    const float* A = d_scratch + aOff;
    float* C = d_scratch + cOff;
    const int t  = threadIdx.x;
    const int tx = t & 15;
    const int ty = t >> 4;
    const int row0 = blockIdx.x * BM;

    unsigned long long acc[TM][TNH];
    #pragma unroll
    for (int jj = 0; jj < TNH; jj++) {
        float2 bv = ((const float2*)bias)[tx + jj * 16];
        unsigned long long bp = pack2(bv.x, bv.y);
        #pragma unroll
        for (int i = 0; i < TM; i++) acc[i][jj] = bp;
    }

    for (int k0 = 0; k0 < K; k0 += BK) {
        // load A tile (BM x BK), store duplicated pairs transposed: As2[kk][m] = (a,a)
        #pragma unroll
        for (int i = t; i < BM * BK / 4; i += 256) {
            int r   = i >> 3;        // 0..63
            int kk4 = i & 7;         // 0..7  (float4 index within BK)
            float4 a = *(const float4*)(A + (size_t)(row0 + r) * K + k0 + kk4 * 4);
            As2[(kk4 * 4 + 0) * (BM + 1) + r] = pack2(a.x, a.x);
            As2[(kk4 * 4 + 1) * (BM + 1) + r] = pack2(a.y, a.y);
            As2[(kk4 * 4 + 2) * (BM + 1) + r] = pack2(a.z, a.z);
            As2[(kk4 * 4 + 3) * (BM + 1) + r] = pack2(a.w, a.w);
        }
        // load W tile (BK x NOUT)
        #pragma unroll
        for (int i = t; i < BK * NOUT / 4; i += 256) {
            int kk = i / (NOUT / 4);
            int c4 = i % (NOUT / 4);
            *(float4*)(Ws + kk * NOUT + c4 * 4) =
                *(const float4*)(W + (size_t)(k0 + kk) * NOUT + c4 * 4);
        }
        __syncthreads();

        const unsigned long long* WsU = (const unsigned long long*)Ws;
        #pragma unroll
        for (int kk = 0; kk < BK; kk++) {
            unsigned long long aP[TM], bP[TNH];
            #pragma unroll
            for (int i = 0; i < TM; i++)
                aP[i] = As2[kk * (BM + 1) + ty * TM + i];
            #pragma unroll
            for (int jj = 0; jj < TNH; jj++)
                bP[jj] = WsU[kk * (NOUT / 2) + tx + jj * 16];
            #pragma unroll
            for (int i = 0; i < TM; i++)
                #pragma unroll
                for (int jj = 0; jj < TNH; jj++)
                    ffma2(acc[i][jj], aP[i], bP[jj]);
        }
        __syncthreads();
    }

    #pragma unroll
    for (int i = 0; i < TM; i++) {
        int row = row0 + ty * TM + i;
        if (row < M) {
            float2* crow = (float2*)(C + (size_t)row * NOUT);
            #pragma unroll
            for (int jj = 0; jj < TNH; jj++) {
                float2 r;
                unpack2(acc[i][jj], r.x, r.y);
                if (RELU) { r.x = fmaxf(r.x, 0.0f); r.y = fmaxf(r.y, 0.0f); }
                crow[tx + jj * 16] = r;
            }
        }
    }
}

// ---------------- edge attention: gather, per-head softmax numerator scatter ----------------
__global__ void edge_kernel(const int* __restrict__ ei) {
    int w = (blockIdx.x * blockDim.x + threadIdx.x) >> 5;
    if (w >= EE) return;
    int lane = threadIdx.x & 31;
    int e0 = ei[w];
    int e1 = ei[EE + w];

    const float4* q4 = (const float4*)(d_scratch + OFF_Q) + (size_t)e1 * 32;
    const float4* k4 = (const float4*)(d_scratch + OFF_K) + (size_t)e0 * 32;
    float4 qv = q4[lane];
    float4 kv = k4[lane];
    float s = qv.x * kv.x + qv.y * kv.y + qv.z * kv.z + qv.w * kv.w;
    s += __shfl_xor_sync(0xffffffffu, s, 1);
    s += __shfl_xor_sync(0xffffffffu, s, 2);   // head dot (HD=16 = 4 lanes)
    s *= 0.25f;                                 // / sqrt(16)
    s = fminf(fmaxf(s, -5.0f), 5.0f);
    float sc = __expf(s);

    const float4* v4 = (const float4*)(d_scratch + OFF_V) + (size_t)e0 * 32;
    float4 vv = v4[lane];
    float4 m = make_float4(vv.x * sc, vv.y * sc, vv.z * sc, vv.w * sc);
    atomicAdd((float4*)(d_scratch + OFF_WV + (size_t)e1 * 128) + lane, m);
    if ((lane & 3) == 0)
        atomicAdd(d_scratch + OFF_Z + (size_t)e1 * 8 + (lane >> 2), sc);
}

// ---------------- attn = wV / (Z + 1e-6) ----------------
__global__ void attn_norm_kernel() {
    int i = blockIdx.x * 256 + threadIdx.x;
    if (i < NN * DD) {
        int node = i >> 7;
        int h = (i >> 4) & 7;
        float z = d_scratch[OFF_Z + (size_t)node * 8 + h] + 1e-6f;
        d_scratch[OFF_ATT + i] = d_scratch[OFF_WV + i] / z;
    }
}

// ---------------- out = LayerNorm(a + b) * g + be, one warp per row ----------------
__global__ void add_ln_kernel(size_t aOff, size_t bOff,
                              const float* __restrict__ g, const float* __restrict__ be,
                              size_t oOff, int M)
{
    int w = (blockIdx.x * blockDim.x + threadIdx.x) >> 5;
    if (w >= M) return;
    int lane = threadIdx.x & 31;
    float4 a = ((const float4*)(d_scratch + aOff + (size_t)w * 128))[lane];
    float4 b = ((const float4*)(d_scratch + bOff + (size_t)w * 128))[lane];
    float v0 = a.x + b.x, v1 = a.y + b.y, v2 = a.z + b.z, v3 = a.w + b.w;

    float s = v0 + v1 + v2 + v3;
    #pragma unroll
    for (int o = 16; o; o >>= 1) s += __shfl_xor_sync(0xffffffffu, s, o);
    float mean = s * (1.0f / 128.0f);
    float d0 = v0 - mean, d1 = v1 - mean, d2 = v2 - mean, d3 = v3 - mean;
    float sq = d0 * d0 + d1 * d1 + d2 * d2 + d3 * d3;
    #pragma unroll
    for (int o = 16; o; o >>= 1) sq += __shfl_xor_sync(0xffffffffu, sq, o);
    float inv = rsqrtf(sq * (1.0f / 128.0f) + 1e-5f);

    float4 gg = ((const float4*)g)[lane];
    float4 bb = ((const float4*)be)[lane];
    float4 o4 = make_float4(d0 * inv * gg.x + bb.x, d1 * inv * gg.y + bb.y,
                            d2 * inv * gg.z + bb.z, d3 * inv * gg.w + bb.w);
    ((float4*)(d_scratch + oOff + (size_t)w * 128))[lane] = o4;
}

// ---------------- column sums of x into acc ----------------
__global__ void colsum_kernel(int M) {
    int d = threadIdx.x;   // 0..127
    const float* x = d_scratch + OFF_X;
    float s = 0.0f;
    for (int r = blockIdx.x; r < M; r += gridDim.x)
        s += x[(size_t)r * 128 + d];
    atomicAdd(&d_scratch[OFF_ACC + d], s);
}

// ---------------- MLP readout: mean -> 64 -> 32 -> 10 ----------------
__global__ void readout_kernel(const float* __restrict__ mW0, const float* __restrict__ mb0,
                               const float* __restrict__ mW1, const float* __restrict__ mb1,
                               const float* __restrict__ mW2, const float* __restrict__ mb2,
                               float* __restrict__ out)
{
    __shared__ float mean[128], h0[64], h1[32];
    int t = threadIdx.x;
    mean[t] = d_scratch[OFF_ACC + t] * (1.0f / (float)NN);
    __syncthreads();
    if (t < 64) {
        float s = mb0[t];
        #pragma unroll 4
        for (int i = 0; i < 128; i++) s += mean[i] * mW0[i * 64 + t];
        h0[t] = fmaxf(s, 0.0f);
    }
    __syncthreads();
    if (t < 32) {
        float s = mb1[t];
        #pragma unroll 4
        for (int i = 0; i < 64; i++) s += h0[i] * mW1[i * 32 + t];
        h1[t] = fmaxf(s, 0.0f);
    }
    __syncthreads();
    if (t < 10) {
        float s = mb2[t];
        #pragma unroll
        for (int i = 0; i < 32; i++) s += h1[i] * mW2[i * 10 + t];
        out[t] = s;
    }
}

// ---------------- host orchestration ----------------
extern "C" void kernel_launch(void* const* d_in, const int* in_sizes, int n_in,
                              void* d_out, int out_size)
{
    const int*   x_idx = (const int*)d_in[0];
    const int*   ei    = (const int*)d_in[1];
    const float* emb   = (const float*)d_in[2];
    const float* Wq  = (const float*)d_in[3];
    const float* bq  = (const float*)d_in[4];
    const float* Wk  = (const float*)d_in[5];
    const float* bk  = (const float*)d_in[6];
    const float* Wv  = (const float*)d_in[7];
    const float* bv  = (const float*)d_in[8];
    const float* Wo  = (const float*)d_in[9];
    const float* bo  = (const float*)d_in[10];
    const float* g1  = (const float*)d_in[11];
    const float* be1 = (const float*)d_in[12];
    const float* Wf1 = (const float*)d_in[13];
    const float* bf1 = (const float*)d_in[14];
    const float* Wf2 = (const float*)d_in[15];
    const float* bf2 = (const float*)d_in[16];
    const float* g2  = (const float*)d_in[17];
    const float* be2 = (const float*)d_in[18];
    const float* mW0 = (const float*)d_in[19];
    const float* mb0 = (const float*)d_in[20];
    const float* mW1 = (const float*)d_in[21];
    const float* mb1 = (const float*)d_in[22];
    const float* mW2 = (const float*)d_in[23];
    const float* mb2 = (const float*)d_in[24];

    const int M = NN;
    const int gemm_grid = (M + 63) / 64;            // 782
    const int elem_grid = (NN * DD + 255) / 256;    // 25000

    embed_kernel<<<elem_grid, 256>>>(x_idx, emb);

    for (int l = 0; l < LL; l++) {
        const float* wq = Wq + (size_t)l * DD * DD;
        const float* wk = Wk + (size_t)l * DD * DD;
        const float* wv = Wv + (size_t)l * DD * DD;
        const float* wo = Wo + (size_t)l * DD * DD;

        gemm_kernel<128, 128, false><<<gemm_grid, 256>>>(OFF_X, wq, bq + l * DD, OFF_Q, M);
        gemm_kernel<128, 128, false><<<gemm_grid, 256>>>(OFF_X, wk, bk + l * DD, OFF_K, M);
        gemm_kernel<128, 128, false><<<gemm_grid, 256>>>(OFF_X, wv, bv + l * DD, OFF_V, M);

        zero_kernel<<<elem_grid, 256>>>(OFF_WV, NN * DD);
        zero_kernel<<<(NN * HH + 255) / 256, 256>>>(OFF_Z, NN * HH);

        edge_kernel<<<EE / 8, 256>>>(ei);
        attn_norm_kernel<<<elem_grid, 256>>>();

        gemm_kernel<128, 128, false><<<gemm_grid, 256>>>(OFF_ATT, wo, bo + l * DD, OFF_Y, M);
        add_ln_kernel<<<(M + 7) / 8, 256>>>(OFF_X, OFF_Y, g1 + l * DD, be1 + l * DD, OFF_X1, M);

        gemm_kernel<128, 256, true ><<<gemm_grid, 256>>>(OFF_Y, Wf1 + (size_t)l * DD * 2 * DD,
                                                         bf1 + l * 2 * DD, OFF_T, M);
        gemm_kernel<256, 128, false><<<gemm_grid, 256>>>(OFF_T, Wf2 + (size_t)l * 2 * DD * DD,
                                                         bf2 + l * DD, OFF_Y2, M);
        add_ln_kernel<<<(M + 7) / 8, 256>>>(OFF_X1, OFF_Y2, g2 + l * DD, be2 + l * DD, OFF_X, M);
    }

    zero_kernel<<<1, 256>>>(OFF_ACC, 128);
    colsum_kernel<<<256, 128>>>(M);
    readout_kernel<<<1, 128>>>(mW0, mb0, mW1, mb1, mW2, mb2, (float*)d_out);
}

// round 6
// speedup vs baseline: 1.6635x; 1.6635x over previous
#include <cuda_runtime.h>
#include <cuda_bf16.h>
#include <cstdint>

// ---------------- problem constants ----------------
#define NN 50000              // nodes
#define EE 800000             // edges
#define DD 128                // model dim
#define HH 8                  // heads
#define LL 3                  // layers

static constexpr size_t NF = (size_t)NN * DD;   // 6,400,000 floats per node tensor

// scratch layout (floats) inside one big device array
static constexpr size_t OFF_X   = 0;
static constexpr size_t OFF_Q   = 1 * NF;
static constexpr size_t OFF_K   = 2 * NF;
static constexpr size_t OFF_V   = 3 * NF;
static constexpr size_t OFF_WV  = 4 * NF;
static constexpr size_t OFF_ATT = 5 * NF;
static constexpr size_t OFF_Y   = 6 * NF;
static constexpr size_t OFF_X1  = 7 * NF;
static constexpr size_t OFF_Y2  = 8 * NF;
static constexpr size_t OFF_T   = 9 * NF;           // 50000 x 256
static constexpr size_t OFF_Z   = 11 * NF;          // 50000 x 8
static constexpr size_t OFF_ACC = 11 * NF + 400000; // 128
static constexpr size_t SCRATCH_FLOATS = 11 * NF + 400000 + 128 + 65536; // pad for tile overreads

__device__ float d_scratch[SCRATCH_FLOATS];

// ---------------- tf32 helpers ----------------
__device__ __forceinline__ uint32_t f2tf32(float f) {
    uint32_t r;
    asm("cvt.rna.tf32.f32 %0, %1;" : "=r"(r) : "f"(f));
    return r;
}
__device__ __forceinline__ void mma_16n8k8(float* c, const uint32_t* a, const uint32_t* b) {
    asm volatile(
        "mma.sync.aligned.m16n8k8.row.col.f32.tf32.tf32.f32 "
        "{%0,%1,%2,%3}, {%4,%5,%6,%7}, {%8,%9}, {%0,%1,%2,%3};"
        : "+f"(c[0]), "+f"(c[1]), "+f"(c[2]), "+f"(c[3])
        : "r"(a[0]), "r"(a[1]), "r"(a[2]), "r"(a[3]), "r"(b[0]), "r"(b[1]));
}

// ---------------- embedding gather ----------------
__global__ void embed_kernel(const int* __restrict__ idx, const float* __restrict__ emb) {
    int i = blockIdx.x * 256 + threadIdx.x;   // 0 .. NN*DD
    if (i < NN * DD) {
        int n = i >> 7;
        int d = i & 127;
        d_scratch[OFF_X + i] = emb[(size_t)idx[n] * DD + d];
    }
}

// ---------------- zero fill ----------------
__global__ void zero_kernel(size_t off, int n) {
    int i = blockIdx.x * 256 + threadIdx.x;
    if (i < n) d_scratch[off + i] = 0.0f;
}

// ---------------- mma.sync tf32 GEMM: C[M,NOUT] = A[M,K] @ W[K,NOUT] + bias ----------------
// BM=128 x BN=128 block tile, 8 warps (4m x 2n), warp tile 32x64, BK=32.
// grid = (ceil(M/128), NOUT/128)
template<int K, int NOUT, bool RELU>
__global__ void __launch_bounds__(256) gemm_mma(size_t aOff, const float* __restrict__ W,
                                                const float* __restrict__ bias, size_t cOff, int M)
{
    constexpr int BM = 128, BN = 128, BK = 32;
    constexpr int BKP = BK + 4;    // padded A row stride (floats)
    constexpr int BNP = BN + 4;    // padded B row stride (floats)

    __shared__ __align__(16) uint32_t As[BM * BKP];   // tf32 bits, row-major [BM][BKP]
    __shared__ __align__(16) uint32_t Bs[BK * BNP];   // tf32 bits, row-major [BK][BNP]

    const int t = threadIdx.x;
    const int wid = t >> 5, lane = t & 31;
    const int qid = lane >> 2;       // 0..7  (thread row group)
    const int rid = lane & 3;        // 0..3  (thread col group)
    const int warp_m = wid & 3;      // 0..3
    const int warp_n = wid >> 2;     // 0..1
    const int wm0 = warp_m * 32;
    const int wn0 = warp_n * 64;
    const int row0 = blockIdx.x * BM;
    const int n0 = blockIdx.y * BN;

    const float* A = d_scratch + aOff;
    float* C = d_scratch + cOff;

    float acc[2][8][4];
    #pragma unroll
    for (int m = 0; m < 2; m++)
        #pragma unroll
        for (int j = 0; j < 8; j++)
            #pragma unroll
            for (int c = 0; c < 4; c++) acc[m][j][c] = 0.0f;

    for (int k0 = 0; k0 < K; k0 += BK) {
        // ---- A tile: 128 x 32 ----
        #pragma unroll
        for (int i = t; i < BM * (BK / 4); i += 256) {
            int r  = i >> 3;
            int c4 = i & 7;
            int grow = row0 + r;
            float4 v = (grow < M) ? *(const float4*)(A + (size_t)grow * K + k0 + c4 * 4)
                                  : make_float4(0.f, 0.f, 0.f, 0.f);
            uint4 u = make_uint4(f2tf32(v.x), f2tf32(v.y), f2tf32(v.z), f2tf32(v.w));
            *(uint4*)(As + r * BKP + c4 * 4) = u;
        }
        // ---- B tile: 32 x 128 from W[k0..k0+32)[n0..n0+128) ----
        #pragma unroll
        for (int i = t; i < BK * (BN / 4); i += 256) {
            int k  = i >> 5;
            int n4 = i & 31;
            float4 v = *(const float4*)(W + (size_t)(k0 + k) * NOUT + n0 + n4 * 4);
            uint4 u = make_uint4(f2tf32(v.x), f2tf32(v.y), f2tf32(v.z), f2tf32(v.w));
            *(uint4*)(Bs + k * BNP + n4 * 4) = u;
        }
        __syncthreads();

        #pragma unroll
        for (int kk = 0; kk < BK / 8; kk++) {
            // A fragments: 2 m-frags
            uint32_t af[2][4];
            #pragma unroll
            for (int m = 0; m < 2; m++) {
                int r = wm0 + m * 16 + qid;
                int c = kk * 8 + rid;
                af[m][0] = As[r * BKP + c];
                af[m][1] = As[(r + 8) * BKP + c];
                af[m][2] = As[r * BKP + c + 4];
                af[m][3] = As[(r + 8) * BKP + c + 4];
            }
            // B fragments: 8 n-frags
            uint32_t bf[8][2];
            #pragma unroll
            for (int j = 0; j < 8; j++) {
                int k = kk * 8 + rid;
                int n = wn0 + j * 8 + qid;
                bf[j][0] = Bs[k * BNP + n];
                bf[j][1] = Bs[(k + 4) * BNP + n];
            }
            #pragma unroll
            for (int m = 0; m < 2; m++)
                #pragma unroll
                for (int j = 0; j < 8; j++)
                    mma_16n8k8(acc[m][j], af[m], bf[j]);
        }
        __syncthreads();
    }

    // ---- epilogue: bias (+ReLU), write float2 pairs ----
    #pragma unroll
    for (int m = 0; m < 2; m++) {
        int r_lo = row0 + wm0 + m * 16 + qid;
        int r_hi = r_lo + 8;
        #pragma unroll
        for (int j = 0; j < 8; j++) {
            int col = n0 + wn0 + j * 8 + 2 * rid;
            float b0 = bias[col], b1 = bias[col + 1];
            float2 lo = make_float2(acc[m][j][0] + b0, acc[m][j][1] + b1);
            float2 hi = make_float2(acc[m][j][2] + b0, acc[m][j][3] + b1);
            if (RELU) {
                lo.x = fmaxf(lo.x, 0.f); lo.y = fmaxf(lo.y, 0.f);
                hi.x = fmaxf(hi.x, 0.f); hi.y = fmaxf(hi.y, 0.f);
            }
            if (r_lo < M) *(float2*)(C + (size_t)r_lo * NOUT + col) = lo;
            if (r_hi < M) *(float2*)(C + (size_t)r_hi * NOUT + col) = hi;
        }
    }
}

// ---------------- edge attention: gather, per-head softmax numerator scatter ----------------
__global__ void edge_kernel(const int* __restrict__ ei) {
    int w = (blockIdx.x * blockDim.x + threadIdx.x) >> 5;
    if (w >= EE) return;
    int lane = threadIdx.x & 31;
    int e0 = ei[w];
    int e1 = ei[EE + w];

    const float4* q4 = (const float4*)(d_scratch + OFF_Q) + (size_t)e1 * 32;
    const float4* k4 = (const float4*)(d_scratch + OFF_K) + (size_t)e0 * 32;
    float4 qv = q4[lane];
    float4 kv = k4[lane];
    float s = qv.x * kv.x + qv.y * kv.y + qv.z * kv.z + qv.w * kv.w;
    s += __shfl_xor_sync(0xffffffffu, s, 1);
    s += __shfl_xor_sync(0xffffffffu, s, 2);   // head dot (HD=16 = 4 lanes)
    s *= 0.25f;                                 // / sqrt(16)
    s = fminf(fmaxf(s, -5.0f), 5.0f);
    float sc = __expf(s);

    const float4* v4 = (const float4*)(d_scratch + OFF_V) + (size_t)e0 * 32;
    float4 vv = v4[lane];
    float4 m = make_float4(vv.x * sc, vv.y * sc, vv.z * sc, vv.w * sc);
    atomicAdd((float4*)(d_scratch + OFF_WV + (size_t)e1 * 128) + lane, m);
    if ((lane & 3) == 0)
        atomicAdd(d_scratch + OFF_Z + (size_t)e1 * 8 + (lane >> 2), sc);
}

// ---------------- attn = wV / (Z + 1e-6) ----------------
__global__ void attn_norm_kernel() {
    int i = blockIdx.x * 256 + threadIdx.x;
    if (i < NN * DD) {
        int node = i >> 7;
        int h = (i >> 4) & 7;
        float z = d_scratch[OFF_Z + (size_t)node * 8 + h] + 1e-6f;
        d_scratch[OFF_ATT + i] = d_scratch[OFF_WV + i] / z;
    }
}

// ---------------- out = LayerNorm(a + b) * g + be, one warp per row ----------------
__global__ void add_ln_kernel(size_t aOff, size_t bOff,
                              const float* __restrict__ g, const float* __restrict__ be,
                              size_t oOff, int M)
{
    int w = (blockIdx.x * blockDim.x + threadIdx.x) >> 5;
    if (w >= M) return;
    int lane = threadIdx.x & 31;
    float4 a = ((const float4*)(d_scratch + aOff + (size_t)w * 128))[lane];
    float4 b = ((const float4*)(d_scratch + bOff + (size_t)w * 128))[lane];
    float v0 = a.x + b.x, v1 = a.y + b.y, v2 = a.z + b.z, v3 = a.w + b.w;

    float s = v0 + v1 + v2 + v3;
    #pragma unroll
    for (int o = 16; o; o >>= 1) s += __shfl_xor_sync(0xffffffffu, s, o);
    float mean = s * (1.0f / 128.0f);
    float d0 = v0 - mean, d1 = v1 - mean, d2 = v2 - mean, d3 = v3 - mean;
    float sq = d0 * d0 + d1 * d1 + d2 * d2 + d3 * d3;
    #pragma unroll
    for (int o = 16; o; o >>= 1) sq += __shfl_xor_sync(0xffffffffu, sq, o);
    float inv = rsqrtf(sq * (1.0f / 128.0f) + 1e-5f);

    float4 gg = ((const float4*)g)[lane];
    float4 bb = ((const float4*)be)[lane];
    float4 o4 = make_float4(d0 * inv * gg.x + bb.x, d1 * inv * gg.y + bb.y,
                            d2 * inv * gg.z + bb.z, d3 * inv * gg.w + bb.w);
    ((float4*)(d_scratch + oOff + (size_t)w * 128))[lane] = o4;
}

// ---------------- column sums of x into acc ----------------
__global__ void colsum_kernel(int M) {
    int d = threadIdx.x;   // 0..127
    const float* x = d_scratch + OFF_X;
    float s = 0.0f;
    for (int r = blockIdx.x; r < M; r += gridDim.x)
        s += x[(size_t)r * 128 + d];
    atomicAdd(&d_scratch[OFF_ACC + d], s);
}

// ---------------- MLP readout: mean -> 64 -> 32 -> 10 ----------------
__global__ void readout_kernel(const float* __restrict__ mW0, const float* __restrict__ mb0,
                               const float* __restrict__ mW1, const float* __restrict__ mb1,
                               const float* __restrict__ mW2, const float* __restrict__ mb2,
                               float* __restrict__ out)
{
    __shared__ float mean[128], h0[64], h1[32];
    int t = threadIdx.x;
    mean[t] = d_scratch[OFF_ACC + t] * (1.0f / (float)NN);
    __syncthreads();
    if (t < 64) {
        float s = mb0[t];
        #pragma unroll 4
        for (int i = 0; i < 128; i++) s += mean[i] * mW0[i * 64 + t];
        h0[t] = fmaxf(s, 0.0f);
    }
    __syncthreads();
    if (t < 32) {
        float s = mb1[t];
        #pragma unroll 4
        for (int i = 0; i < 64; i++) s += h0[i] * mW1[i * 32 + t];
        h1[t] = fmaxf(s, 0.0f);
    }
    __syncthreads();
    if (t < 10) {
        float s = mb2[t];
        #pragma unroll
        for (int i = 0; i < 32; i++) s += h1[i] * mW2[i * 10 + t];
        out[t] = s;
    }
}

// ---------------- host orchestration ----------------
extern "C" void kernel_launch(void* const* d_in, const int* in_sizes, int n_in,
                              void* d_out, int out_size)
{
    const int*   x_idx = (const int*)d_in[0];
    const int*   ei    = (const int*)d_in[1];
    const float* emb   = (const float*)d_in[2];
    const float* Wq  = (const float*)d_in[3];
    const float* bq  = (const float*)d_in[4];
    const float* Wk  = (const float*)d_in[5];
    const float* bk  = (const float*)d_in[6];
    const float* Wv  = (const float*)d_in[7];
    const float* bv  = (const float*)d_in[8];
    const float* Wo  = (const float*)d_in[9];
    const float* bo  = (const float*)d_in[10];
    const float* g1  = (const float*)d_in[11];
    const float* be1 = (const float*)d_in[12];
    const float* Wf1 = (const float*)d_in[13];
    const float* bf1 = (const float*)d_in[14];
    const float* Wf2 = (const float*)d_in[15];
    const float* bf2 = (const float*)d_in[16];
    const float* g2  = (const float*)d_in[17];
    const float* be2 = (const float*)d_in[18];
    const float* mW0 = (const float*)d_in[19];
    const float* mb0 = (const float*)d_in[20];
    const float* mW1 = (const float*)d_in[21];
    const float* mb1 = (const float*)d_in[22];
    const float* mW2 = (const float*)d_in[23];
    const float* mb2 = (const float*)d_in[24];

    const int M = NN;
    const dim3 g128((M + 127) / 128, 1);            // 391 x 1
    const dim3 g256((M + 127) / 128, 2);            // 391 x 2 (NOUT=256)
    const int elem_grid = (NN * DD + 255) / 256;    // 25000

    embed_kernel<<<elem_grid, 256>>>(x_idx, emb);

    for (int l = 0; l < LL; l++) {
        const float* wq = Wq + (size_t)l * DD * DD;
        const float* wk = Wk + (size_t)l * DD * DD;
        const float* wv = Wv + (size_t)l * DD * DD;
        const float* wo = Wo + (size_t)l * DD * DD;

        gemm_mma<128, 128, false><<<g128, 256>>>(OFF_X, wq, bq + l * DD, OFF_Q, M);
        gemm_mma<128, 128, false><<<g128, 256>>>(OFF_X, wk, bk + l * DD, OFF_K, M);
        gemm_mma<128, 128, false><<<g128, 256>>>(OFF_X, wv, bv + l * DD, OFF_V, M);

        zero_kernel<<<elem_grid, 256>>>(OFF_WV, NN * DD);
        zero_kernel<<<(NN * HH + 255) / 256, 256>>>(OFF_Z, NN * HH);

        edge_kernel<<<EE / 8, 256>>>(ei);
        attn_norm_kernel<<<elem_grid, 256>>>();

        gemm_mma<128, 128, false><<<g128, 256>>>(OFF_ATT, wo, bo + l * DD, OFF_Y, M);
        add_ln_kernel<<<(M + 7) / 8, 256>>>(OFF_X, OFF_Y, g1 + l * DD, be1 + l * DD, OFF_X1, M);

        gemm_mma<128, 256, true ><<<g256, 256>>>(OFF_Y, Wf1 + (size_t)l * DD * 2 * DD,
                                                 bf1 + l * 2 * DD, OFF_T, M);
        gemm_mma<256, 128, false><<<g128, 256>>>(OFF_T, Wf2 + (size_t)l * 2 * DD * DD,
                                                 bf2 + l * DD, OFF_Y2, M);
        add_ln_kernel<<<(M + 7) / 8, 256>>>(OFF_X1, OFF_Y2, g2 + l * DD, be2 + l * DD, OFF_X, M);
    }

    zero_kernel<<<1, 256>>>(OFF_ACC, 128);
    colsum_kernel<<<256, 128>>>(M);
    readout_kernel<<<1, 128>>>(mW0, mb0, mW1, mb1, mW2, mb2, (float*)d_out);
}

// round 8
// speedup vs baseline: 1.9909x; 1.1968x over previous
#include <cuda_runtime.h>
#include <cuda_bf16.h>
#include <cstdint>

// ---------------- problem constants ----------------
#define NN 50000              // nodes
#define EE 800000             // edges
#define DD 128                // model dim
#define HH 8                  // heads
#define LL 3                  // layers

static constexpr size_t NF = (size_t)NN * DD;   // 6,400,000 floats per node tensor

// scratch layout (floats) inside one big device array
static constexpr size_t OFF_X   = 0;
static constexpr size_t OFF_Q   = 1 * NF;
static constexpr size_t OFF_K   = 2 * NF;
static constexpr size_t OFF_V   = 3 * NF;
static constexpr size_t OFF_ATT = 5 * NF;
static constexpr size_t OFF_Y   = 6 * NF;
static constexpr size_t OFF_X1  = 7 * NF;
static constexpr size_t OFF_Y2  = 8 * NF;
static constexpr size_t OFF_T   = 9 * NF;           // 50000 x 256
static constexpr size_t OFF_ACC = 11 * NF;          // 128
static constexpr size_t OFF_INT = 11 * NF + 256;    // int-region base (float units)
// int layout within OFF_INT (int units): rowptr[NN+1] | pad | cursor[NN] | pad | srcs[EE]
static constexpr size_t I_ROWPTR = 0;
static constexpr size_t I_CURSOR = NN + 64;
static constexpr size_t I_SRCS   = 2 * NN + 128;
static constexpr size_t SCRATCH_FLOATS = OFF_INT + (2 * NN + 128 + EE) + 65536;

__device__ float d_scratch[SCRATCH_FLOATS];

// ---------------- tf32 helpers ----------------
__device__ __forceinline__ uint32_t f2tf32(float f) {
    uint32_t r;
    asm("cvt.rna.tf32.f32 %0, %1;" : "=r"(r) : "f"(f));
    return r;
}
__device__ __forceinline__ void mma_16n8k8(float* c, const uint32_t* a, const uint32_t* b) {
    asm volatile(
        "mma.sync.aligned.m16n8k8.row.col.f32.tf32.tf32.f32 "
        "{%0,%1,%2,%3}, {%4,%5,%6,%7}, {%8,%9}, {%0,%1,%2,%3};"
        : "+f"(c[0]), "+f"(c[1]), "+f"(c[2]), "+f"(c[3])
        : "r"(a[0]), "r"(a[1]), "r"(a[2]), "r"(a[3]), "r"(b[0]), "r"(b[1]));
}

// ---------------- embedding gather ----------------
__global__ void embed_kernel(const int* __restrict__ idx, const float* __restrict__ emb) {
    int i = blockIdx.x * 256 + threadIdx.x;   // 0 .. NN*DD
    if (i < NN * DD) {
        int n = i >> 7;
        int d = i & 127;
        d_scratch[OFF_X + i] = emb[(size_t)idx[n] * DD + d];
    }
}

// ---------------- zero fill ----------------
__global__ void zero_kernel(size_t off, int n) {
    int i = blockIdx.x * 256 + threadIdx.x;
    if (i < n) d_scratch[off + i] = 0.0f;
}

// ---------------- CSR build (once per launch; edge_index is call-invariant) ----------------
__global__ void csr_zero_counts() {
    int i = blockIdx.x * 256 + threadIdx.x;
    int* cnt = (int*)(d_scratch + OFF_INT) + I_CURSOR;
    if (i < NN) cnt[i] = 0;
}
__global__ void csr_hist(const int* __restrict__ ei) {
    int i = blockIdx.x * 256 + threadIdx.x;
    int* cnt = (int*)(d_scratch + OFF_INT) + I_CURSOR;
    if (i < EE) atomicAdd(&cnt[ei[EE + i]], 1);
}
// single block of 1024 threads: exclusive scan of counts -> rowptr, and cursor=rowptr
__global__ void csr_scan() {
    __shared__ int ssum[1024];
    int* ip = (int*)(d_scratch + OFF_INT);
    const int* cnt = ip + I_CURSOR;
    int* rowptr = ip + I_ROWPTR;
    int* cursor = ip + I_CURSOR;       // overwritten in pass 2 (after re-read below)
    int t = threadIdx.x;
    const int CH = (NN + 1023) / 1024;
    int b0 = t * CH;
    int b1 = min(b0 + CH, NN);
    int s = 0;
    for (int i = b0; i < b1; i++) s += cnt[i];
    ssum[t] = s;
    __syncthreads();
    for (int o = 1; o < 1024; o <<= 1) {
        int v = (t >= o) ? ssum[t - o] : 0;
        __syncthreads();
        ssum[t] += v;
        __syncthreads();
    }
    int run = ssum[t] - s;             // exclusive prefix of this chunk
    for (int i = b0; i < b1; i++) {
        int c = cnt[i];                // read before overwrite (same thread owns slot)
        rowptr[i] = run;
        cursor[i] = run;
        run += c;
    }
    if (t == 1023) rowptr[NN] = run;   // == EE
}
__global__ void csr_scatter(const int* __restrict__ ei) {
    int i = blockIdx.x * 256 + threadIdx.x;
    int* ip = (int*)(d_scratch + OFF_INT);
    if (i < EE) {
        int d = ei[EE + i];
        int pos = atomicAdd(&ip[I_CURSOR + d], 1);
        ip[I_SRCS + pos] = ei[i];      // store source node e0
    }
}

// ---------------- fused gather attention: per-node register accumulation, no atomics ----------------
// one warp per destination node; writes attn = wV / (Z + 1e-6) directly
__global__ void attn_gather_kernel() {
    int node = (blockIdx.x * blockDim.x + threadIdx.x) >> 5;
    if (node >= NN) return;
    int lane = threadIdx.x & 31;
    const int* ip = (const int*)(d_scratch + OFF_INT);
    const float4* Q4 = (const float4*)(d_scratch + OFF_Q);
    const float4* K4 = (const float4*)(d_scratch + OFF_K);
    const float4* V4 = (const float4*)(d_scratch + OFF_V);

    float4 qv = Q4[(size_t)node * 32 + lane];
    float4 acc = make_float4(0.f, 0.f, 0.f, 0.f);
    float z = 0.f;

    int beg = ip[I_ROWPTR + node];
    int end = ip[I_ROWPTR + node + 1];
    for (int i = beg; i < end; i++) {
        int src = ip[I_SRCS + i];
        float4 kv = K4[(size_t)src * 32 + lane];
        float4 vv = V4[(size_t)src * 32 + lane];
        float s = qv.x * kv.x + qv.y * kv.y + qv.z * kv.z + qv.w * kv.w;
        s += __shfl_xor_sync(0xffffffffu, s, 1);
        s += __shfl_xor_sync(0xffffffffu, s, 2);   // head dot (HD=16 = 4 lanes)
        s = fminf(fmaxf(s * 0.25f, -5.0f), 5.0f);
        float sc = __expf(s);
        acc.x += vv.x * sc; acc.y += vv.y * sc;
        acc.z += vv.z * sc; acc.w += vv.w * sc;
        z += sc;
    }
    float inv = 1.0f / (z + 1e-6f);
    float4 o = make_float4(acc.x * inv, acc.y * inv, acc.z * inv, acc.w * inv);
    ((float4*)(d_scratch + OFF_ATT))[(size_t)node * 32 + lane] = o;
}

// ---------------- mma.sync tf32 GEMM: C[M,NOUT] = A[M,K] @ W[K,NOUT] + bias ----------------
template<int K, int NOUT, bool RELU>
__global__ void __launch_bounds__(256) gemm_mma(size_t aOff, const float* __restrict__ W,
                                                const float* __restrict__ bias, size_t cOff, int M)
{
    constexpr int BM = 128, BN = 128, BK = 32;
    constexpr int BKP = BK + 4;
    constexpr int BNP = BN + 4;

    __shared__ __align__(16) uint32_t As[BM * BKP];
    __shared__ __align__(16) uint32_t Bs[BK * BNP];

    const int t = threadIdx.x;
    const int wid = t >> 5, lane = t & 31;
    const int qid = lane >> 2;
    const int rid = lane & 3;
    const int warp_m = wid & 3;
    const int warp_n = wid >> 2;
    const int wm0 = warp_m * 32;
    const int wn0 = warp_n * 64;
    const int row0 = blockIdx.x * BM;
    const int n0 = blockIdx.y * BN;

    const float* A = d_scratch + aOff;
    float* C = d_scratch + cOff;

    float acc[2][8][4];
    #pragma unroll
    for (int m = 0; m < 2; m++)
        #pragma unroll
        for (int j = 0; j < 8; j++)
            #pragma unroll
            for (int c = 0; c < 4; c++) acc[m][j][c] = 0.0f;

    for (int k0 = 0; k0 < K; k0 += BK) {
        #pragma unroll
        for (int i = t; i < BM * (BK / 4); i += 256) {
            int r  = i >> 3;
            int c4 = i & 7;
            int grow = row0 + r;
            float4 v = (grow < M) ? *(const float4*)(A + (size_t)grow * K + k0 + c4 * 4)
                                  : make_float4(0.f, 0.f, 0.f, 0.f);
            uint4 u = make_uint4(f2tf32(v.x), f2tf32(v.y), f2tf32(v.z), f2tf32(v.w));
            *(uint4*)(As + r * BKP + c4 * 4) = u;
        }
        #pragma unroll
        for (int i = t; i < BK * (BN / 4); i += 256) {
            int k  = i >> 5;
            int n4 = i & 31;
            float4 v = *(const float4*)(W + (size_t)(k0 + k) * NOUT + n0 + n4 * 4);
            uint4 u = make_uint4(f2tf32(v.x), f2tf32(v.y), f2tf32(v.z), f2tf32(v.w));
            *(uint4*)(Bs + k * BNP + n4 * 4) = u;
        }
        __syncthreads();

        #pragma unroll
        for (int kk = 0; kk < BK / 8; kk++) {
            uint32_t af[2][4];
            #pragma unroll
            for (int m = 0; m < 2; m++) {
                int r = wm0 + m * 16 + qid;
                int c = kk * 8 + rid;
                af[m][0] = As[r * BKP + c];
                af[m][1] = As[(r + 8) * BKP + c];
                af[m][2] = As[r * BKP + c + 4];
                af[m][3] = As[(r + 8) * BKP + c + 4];
            }
            uint32_t bf[8][2];
            #pragma unroll
            for (int j = 0; j < 8; j++) {
                int k = kk * 8 + rid;
                int n = wn0 + j * 8 + qid;
                bf[j][0] = Bs[k * BNP + n];
                bf[j][1] = Bs[(k + 4) * BNP + n];
            }
            #pragma unroll
            for (int m = 0; m < 2; m++)
                #pragma unroll
                for (int j = 0; j < 8; j++)
                    mma_16n8k8(acc[m][j], af[m], bf[j]);
        }
        __syncthreads();
    }

    #pragma unroll
    for (int m = 0; m < 2; m++) {
        int r_lo = row0 + wm0 + m * 16 + qid;
        int r_hi = r_lo + 8;
        #pragma unroll
        for (int j = 0; j < 8; j++) {
            int col = n0 + wn0 + j * 8 + 2 * rid;
            float b0 = bias[col], b1 = bias[col + 1];
            float2 lo = make_float2(acc[m][j][0] + b0, acc[m][j][1] + b1);
            float2 hi = make_float2(acc[m][j][2] + b0, acc[m][j][3] + b1);
            if (RELU) {
                lo.x = fmaxf(lo.x, 0.f); lo.y = fmaxf(lo.y, 0.f);
                hi.x = fmaxf(hi.x, 0.f); hi.y = fmaxf(hi.y, 0.f);
            }
            if (r_lo < M) *(float2*)(C + (size_t)r_lo * NOUT + col) = lo;
            if (r_hi < M) *(float2*)(C + (size_t)r_hi * NOUT + col) = hi;
        }
    }
}

// ---------------- out = LayerNorm(a + b) * g + be, one warp per row ----------------
__global__ void add_ln_kernel(size_t aOff, size_t bOff,
                              const float* __restrict__ g, const float* __restrict__ be,
                              size_t oOff, int M)
{
    int w = (blockIdx.x * blockDim.x + threadIdx.x) >> 5;
    if (w >= M) return;
    int lane = threadIdx.x & 31;
    float4 a = ((const float4*)(d_scratch + aOff + (size_t)w * 128))[lane];
    float4 b = ((const float4*)(d_scratch + bOff + (size_t)w * 128))[lane];
    float v0 = a.x + b.x, v1 = a.y + b.y, v2 = a.z + b.z, v3 = a.w + b.w;

    float s = v0 + v1 + v2 + v3;
    #pragma unroll
    for (int o = 16; o; o >>= 1) s += __shfl_xor_sync(0xffffffffu, s, o);
    float mean = s * (1.0f / 128.0f);
    float d0 = v0 - mean, d1 = v1 - mean, d2 = v2 - mean, d3 = v3 - mean;
    float sq = d0 * d0 + d1 * d1 + d2 * d2 + d3 * d3;
    #pragma unroll
    for (int o = 16; o; o >>= 1) sq += __shfl_xor_sync(0xffffffffu, sq, o);
    float inv = rsqrtf(sq * (1.0f / 128.0f) + 1e-5f);

    float4 gg = ((const float4*)g)[lane];
    float4 bb = ((const float4*)be)[lane];
    float4 o4 = make_float4(d0 * inv * gg.x + bb.x, d1 * inv * gg.y + bb.y,
                            d2 * inv * gg.z + bb.z, d3 * inv * gg.w + bb.w);
    ((float4*)(d_scratch + oOff + (size_t)w * 128))[lane] = o4;
}

// ---------------- column sums of x into acc ----------------
__global__ void colsum_kernel(int M) {
    int d = threadIdx.x;   // 0..127
    const float* x = d_scratch + OFF_X;
    float s = 0.0f;
    for (int r = blockIdx.x; r < M; r += gridDim.x)
        s += x[(size_t)r * 128 + d];
    atomicAdd(&d_scratch[OFF_ACC + d], s);
}

// ---------------- MLP readout: mean -> 64 -> 32 -> 10 ----------------
__global__ void readout_kernel(const float* __restrict__ mW0, const float* __restrict__ mb0,
                               const float* __restrict__ mW1, const float* __restrict__ mb1,
                               const float* __restrict__ mW2, const float* __restrict__ mb2,
                               float* __restrict__ out)
{
    __shared__ float mean[128], h0[64], h1[32];
    int t = threadIdx.x;
    mean[t] = d_scratch[OFF_ACC + t] * (1.0f / (float)NN);
    __syncthreads();
    if (t < 64) {
        float s = mb0[t];
        #pragma unroll 4
        for (int i = 0; i < 128; i++) s += mean[i] * mW0[i * 64 + t];
        h0[t] = fmaxf(s, 0.0f);
    }
    __syncthreads();
    if (t < 32) {
        float s = mb1[t];
        #pragma unroll 4
        for (int i = 0; i < 64; i++) s += h0[i] * mW1[i * 32 + t];
        h1[t] = fmaxf(s, 0.0f);
    }
    __syncthreads();
    if (t < 10) {
        float s = mb2[t];
        #pragma unroll
        for (int i = 0; i < 32; i++) s += h1[i] * mW2[i * 10 + t];
        out[t] = s;
    }
}

// ---------------- host orchestration ----------------
extern "C" void kernel_launch(void* const* d_in, const int* in_sizes, int n_in,
                              void* d_out, int out_size)
{
    const int*   x_idx = (const int*)d_in[0];
    const int*   ei    = (const int*)d_in[1];
    const float* emb   = (const float*)d_in[2];
    const float* Wq  = (const float*)d_in[3];
    const float* bq  = (const float*)d_in[4];
    const float* Wk  = (const float*)d_in[5];
    const float* bk  = (const float*)d_in[6];
    const float* Wv  = (const float*)d_in[7];
    const float* bv  = (const float*)d_in[8];
    const float* Wo  = (const float*)d_in[9];
    const float* bo  = (const float*)d_in[10];
    const float* g1  = (const float*)d_in[11];
    const float* be1 = (const float*)d_in[12];
    const float* Wf1 = (const float*)d_in[13];
    const float* bf1 = (const float*)d_in[14];
    const float* Wf2 = (const float*)d_in[15];
    const float* bf2 = (const float*)d_in[16];
    const float* g2  = (const float*)d_in[17];
    const float* be2 = (const float*)d_in[18];
    const float* mW0 = (const float*)d_in[19];
    const float* mb0 = (const float*)d_in[20];
    const float* mW1 = (const float*)d_in[21];
    const float* mb1 = (const float*)d_in[22];
    const float* mW2 = (const float*)d_in[23];
    const float* mb2 = (const float*)d_in[24];

    const int M = NN;
    const dim3 g128((M + 127) / 128, 1);            // 391 x 1
    const dim3 g256((M + 127) / 128, 2);            // 391 x 2 (NOUT=256)
    const int elem_grid = (NN * DD + 255) / 256;    // 25000
    const int edge_grid = (EE + 255) / 256;         // 3125
    const int node_grid = (NN + 255) / 256;         // 196
    const int warp_grid = (NN * 32 + 255) / 256;    // 6250

    embed_kernel<<<elem_grid, 256>>>(x_idx, emb);

    // CSR build (edge_index invariant across layers)
    csr_zero_counts<<<node_grid, 256>>>();
    csr_hist<<<edge_grid, 256>>>(ei);
    csr_scan<<<1, 1024>>>();
    csr_scatter<<<edge_grid, 256>>>(ei);

    for (int l = 0; l < LL; l++) {
        const float* wq = Wq + (size_t)l * DD * DD;
        const float* wk = Wk + (size_t)l * DD * DD;
        const float* wv = Wv + (size_t)l * DD * DD;
        const float* wo = Wo + (size_t)l * DD * DD;

        gemm_mma<128, 128, false><<<g128, 256>>>(OFF_X, wq, bq + l * DD, OFF_Q, M);
        gemm_mma<128, 128, false><<<g128, 256>>>(OFF_X, wk, bk + l * DD, OFF_K, M);
        gemm_mma<128, 128, false><<<g128, 256>>>(OFF_X, wv, bv + l * DD, OFF_V, M);

        attn_gather_kernel<<<warp_grid, 256>>>();

        gemm_mma<128, 128, false><<<g128, 256>>>(OFF_ATT, wo, bo + l * DD, OFF_Y, M);
        add_ln_kernel<<<(M + 7) / 8, 256>>>(OFF_X, OFF_Y, g1 + l * DD, be1 + l * DD, OFF_X1, M);

        gemm_mma<128, 256, true ><<<g256, 256>>>(OFF_Y, Wf1 + (size_t)l * DD * 2 * DD,
                                                 bf1 + l * 2 * DD, OFF_T, M);
        gemm_mma<256, 128, false><<<g128, 256>>>(OFF_T, Wf2 + (size_t)l * 2 * DD * DD,
                                                 bf2 + l * DD, OFF_Y2, M);
        add_ln_kernel<<<(M + 7) / 8, 256>>>(OFF_X1, OFF_Y2, g2 + l * DD, be2 + l * DD, OFF_X, M);
    }

    zero_kernel<<<1, 256>>>(OFF_ACC, 128);
    colsum_kernel<<<256, 128>>>(M);
    readout_kernel<<<1, 128>>>(mW0, mb0, mW1, mb1, mW2, mb2, (float*)d_out);
}

// round 17
// speedup vs baseline: 2.1101x; 1.0599x over previous
#include <cuda_runtime.h>
#include <cuda_bf16.h>
#include <cstdint>

// ---------------- problem constants ----------------
#define NN 50000              // nodes
#define EE 800000             // edges
#define DD 128                // model dim
#define HH 8                  // heads
#define LL 3                  // layers

static constexpr size_t NF = (size_t)NN * DD;   // 6,400,000 floats per node tensor

// scratch layout (floats) inside one big device array
static constexpr size_t OFF_X   = 0;
static constexpr size_t OFF_Q   = 1 * NF;
static constexpr size_t OFF_K   = 2 * NF;
static constexpr size_t OFF_V   = 3 * NF;
static constexpr size_t OFF_ATT = 5 * NF;
static constexpr size_t OFF_Y   = 6 * NF;
static constexpr size_t OFF_X1  = 7 * NF;
static constexpr size_t OFF_Y2  = 8 * NF;
static constexpr size_t OFF_T   = 9 * NF;           // 50000 x 256
static constexpr size_t OFF_ACC = 11 * NF;          // 128
static constexpr size_t OFF_INT = 11 * NF + 256;    // int-region base (float units)
// int layout within OFF_INT (int units): rowptr[NN+1] | pad | cursor[NN] | pad | srcs[EE]
static constexpr size_t I_ROWPTR = 0;
static constexpr size_t I_CURSOR = NN + 64;
static constexpr size_t I_SRCS   = 2 * NN + 128;
static constexpr size_t SCRATCH_FLOATS = OFF_INT + (2 * NN + 128 + EE) + 65536;

__device__ float d_scratch[SCRATCH_FLOATS];

// ---------------- helpers ----------------
__device__ __forceinline__ uint32_t f2tf32(float f) {
    uint32_t r;
    asm("cvt.rna.tf32.f32 %0, %1;" : "=r"(r) : "f"(f));
    return r;
}
__device__ __forceinline__ void mma_16n8k8(float* c, const uint32_t* a, const uint32_t* b) {
    asm volatile(
        "mma.sync.aligned.m16n8k8.row.col.f32.tf32.tf32.f32 "
        "{%0,%1,%2,%3}, {%4,%5,%6,%7}, {%8,%9}, {%0,%1,%2,%3};"
        : "+f"(c[0]), "+f"(c[1]), "+f"(c[2]), "+f"(c[3])
        : "r"(a[0]), "r"(a[1]), "r"(a[2]), "r"(a[3]), "r"(b[0]), "r"(b[1]));
}
__device__ __forceinline__ uint32_t smem_u32(const void* p) {
    uint32_t a;
    asm("{ .reg .u64 t; cvta.to.shared.u64 t, %1; cvt.u32.u64 %0, t; }" : "=r"(a) : "l"(p));
    return a;
}
__device__ __forceinline__ void cp_async16(uint32_t dst, const void* src) {
    asm volatile("cp.async.cg.shared.global [%0], [%1], 16;" :: "r"(dst), "l"(src));
}
#define CP_COMMIT() asm volatile("cp.async.commit_group;" ::: "memory")
#define CP_WAIT1()  asm volatile("cp.async.wait_group 1;" ::: "memory")
#define CP_WAIT0()  asm volatile("cp.async.wait_group 0;" ::: "memory")

// ---------------- embedding gather ----------------
__global__ void embed_kernel(const int* __restrict__ idx, const float* __restrict__ emb) {
    int i = blockIdx.x * 256 + threadIdx.x;   // 0 .. NN*DD
    if (i < NN * DD) {
        int n = i >> 7;
        int d = i & 127;
        d_scratch[OFF_X + i] = emb[(size_t)idx[n] * DD + d];
    }
}

// ---------------- zero fill ----------------
__global__ void zero_kernel(size_t off, int n) {
    int i = blockIdx.x * 256 + threadIdx.x;
    if (i < n) d_scratch[off + i] = 0.0f;
}

// ---------------- CSR build (once per launch; edge_index is call-invariant) ----------------
__global__ void csr_zero_counts() {
    int i = blockIdx.x * 256 + threadIdx.x;
    int* cnt = (int*)(d_scratch + OFF_INT) + I_CURSOR;
    if (i < NN) cnt[i] = 0;
}
__global__ void csr_hist(const int* __restrict__ ei) {
    int i = blockIdx.x * 256 + threadIdx.x;
    int* cnt = (int*)(d_scratch + OFF_INT) + I_CURSOR;
    if (i < EE) atomicAdd(&cnt[ei[EE + i]], 1);
}
// single block of 1024 threads: smem-staged exclusive scan of counts -> rowptr, cursor=rowptr
__global__ void csr_scan() {
    extern __shared__ int scnt[];          // NN ints (200 KB dynamic)
    __shared__ int ssum[1024];
    int* ip = (int*)(d_scratch + OFF_INT);
    int* rowptr = ip + I_ROWPTR;
    int* cursor = ip + I_CURSOR;           // holds counts on entry
    int t = threadIdx.x;

    // coalesced load counts -> smem
    for (int i = t; i < NN; i += 1024) scnt[i] = cursor[i];
    __syncthreads();

    const int CH = (NN + 1023) / 1024;     // 49
    int b0 = min(t * CH, NN);
    int b1 = min(b0 + CH, NN);
    int s = 0;
    for (int i = b0; i < b1; i++) s += scnt[i];
    ssum[t] = s;
    __syncthreads();
    for (int o = 1; o < 1024; o <<= 1) {
        int v = (t >= o) ? ssum[t - o] : 0;
        __syncthreads();
        ssum[t] += v;
        __syncthreads();
    }
    int run = ssum[t] - s;                 // exclusive prefix of this chunk
    for (int i = b0; i < b1; i++) {
        int c = scnt[i];
        scnt[i] = run;                     // in-place: own chunk only
        run += c;
    }
    __syncthreads();
    // coalesced write-out
    for (int i = t; i < NN; i += 1024) {
        int v = scnt[i];
        rowptr[i] = v;
        cursor[i] = v;
    }
    if (t == 1023) rowptr[NN] = ssum[1023];  // == EE
}
__global__ void csr_scatter(const int* __restrict__ ei) {
    int i = blockIdx.x * 256 + threadIdx.x;
    int* ip = (int*)(d_scratch + OFF_INT);
    if (i < EE) {
        int d = ei[EE + i];
        int pos = atomicAdd(&ip[I_CURSOR + d], 1);
        ip[I_SRCS + pos] = ei[i];      // store source node e0
    }
}

// ---------------- fused gather attention: per-node register accumulation, no atomics ----------------
// one warp per destination node, 2-way edge ILP; writes attn = wV / (Z + 1e-6) directly
__global__ void attn_gather_kernel() {
    int node = (blockIdx.x * blockDim.x + threadIdx.x) >> 5;
    if (node >= NN) return;
    int lane = threadIdx.x & 31;
    const int* ip = (const int*)(d_scratch + OFF_INT);
    const float4* Q4 = (const float4*)(d_scratch + OFF_Q);
    const float4* K4 = (const float4*)(d_scratch + OFF_K);
    const float4* V4 = (const float4*)(d_scratch + OFF_V);

    float4 qv = Q4[(size_t)node * 32 + lane];
    float4 acc0 = make_float4(0.f, 0.f, 0.f, 0.f);
    float4 acc1 = make_float4(0.f, 0.f, 0.f, 0.f);
    float z0 = 0.f, z1 = 0.f;

    int beg = ip[I_ROWPTR + node];
    int end = ip[I_ROWPTR + node + 1];
    int i = beg;
    for (; i + 1 < end; i += 2) {
        int s0 = ip[I_SRCS + i];
        int s1 = ip[I_SRCS + i + 1];
        float4 kv0 = K4[(size_t)s0 * 32 + lane];
        float4 kv1 = K4[(size_t)s1 * 32 + lane];
        float4 vv0 = V4[(size_t)s0 * 32 + lane];
        float4 vv1 = V4[(size_t)s1 * 32 + lane];

        float d0 = qv.x * kv0.x + qv.y * kv0.y + qv.z * kv0.z + qv.w * kv0.w;
        float d1 = qv.x * kv1.x + qv.y * kv1.y + qv.z * kv1.z + qv.w * kv1.w;
        d0 += __shfl_xor_sync(0xffffffffu, d0, 1);
        d1 += __shfl_xor_sync(0xffffffffu, d1, 1);
        d0 += __shfl_xor_sync(0xffffffffu, d0, 2);
        d1 += __shfl_xor_sync(0xffffffffu, d1, 2);
        d0 = fminf(fmaxf(d0 * 0.25f, -5.0f), 5.0f);
        d1 = fminf(fmaxf(d1 * 0.25f, -5.0f), 5.0f);
        float sc0 = __expf(d0);
        float sc1 = __expf(d1);

        acc0.x += vv0.x * sc0; acc0.y += vv0.y * sc0;
        acc0.z += vv0.z * sc0; acc0.w += vv0.w * sc0;
        acc1.x += vv1.x * sc1; acc1.y += vv1.y * sc1;
        acc1.z += vv1.z * sc1; acc1.w += vv1.w * sc1;
        z0 += sc0; z1 += sc1;
    }
    if (i < end) {
        int s0 = ip[I_SRCS + i];
        float4 kv0 = K4[(size_t)s0 * 32 + lane];
        float4 vv0 = V4[(size_t)s0 * 32 + lane];
        float d0 = qv.x * kv0.x + qv.y * kv0.y + qv.z * kv0.z + qv.w * kv0.w;
        d0 += __shfl_xor_sync(0xffffffffu, d0, 1);
        d0 += __shfl_xor_sync(0xffffffffu, d0, 2);
        d0 = fminf(fmaxf(d0 * 0.25f, -5.0f), 5.0f);
        float sc0 = __expf(d0);
        acc0.x += vv0.x * sc0; acc0.y += vv0.y * sc0;
        acc0.z += vv0.z * sc0; acc0.w += vv0.w * sc0;
        z0 += sc0;
    }

    float z = z0 + z1;
    float inv = 1.0f / (z + 1e-6f);
    float4 o = make_float4((acc0.x + acc1.x) * inv, (acc0.y + acc1.y) * inv,
                           (acc0.z + acc1.z) * inv, (acc0.w + acc1.w) * inv);
    ((float4*)(d_scratch + OFF_ATT))[(size_t)node * 32 + lane] = o;
}

// ---------------- cp.async double-buffered mma.sync tf32 GEMM ----------------
// C[M,NOUT] = A[M,K] @ W[K,NOUT] + bias. BM=128 x BN=128, 8 warps (4m x 2n), BK=32, 2 stages.
template<int K, int NOUT, bool RELU>
__global__ void __launch_bounds__(256) gemm_mma(size_t aOff, const float* __restrict__ W,
                                                const float* __restrict__ bias, size_t cOff, int M)
{
    constexpr int BM = 128, BN = 128, BK = 32;
    constexpr int BKP = BK + 4;    // 36 floats = 144B (16B aligned)
    constexpr int BNP = BN + 4;    // 132 floats = 528B (16B aligned)
    constexpr int NT = K / BK;

    extern __shared__ float smf[];
    float* Abuf[2] = { smf, smf + BM * BKP };
    float* Bbuf[2] = { smf + 2 * BM * BKP, smf + 2 * BM * BKP + BK * BNP };

    const int t = threadIdx.x;
    const int wid = t >> 5, lane = t & 31;
    const int qid = lane >> 2;
    const int rid = lane & 3;
    const int warp_m = wid & 3;
    const int warp_n = wid >> 2;
    const int wm0 = warp_m * 32;
    const int wn0 = warp_n * 64;
    const int row0 = blockIdx.x * BM;
    const int n0 = blockIdx.y * BN;

    const float* A = d_scratch + aOff;
    float* C = d_scratch + cOff;

    const uint32_t sA[2] = { smem_u32(Abuf[0]), smem_u32(Abuf[1]) };
    const uint32_t sB[2] = { smem_u32(Bbuf[0]), smem_u32(Bbuf[1]) };

    auto load_tile = [&](int it, int buf) {
        #pragma unroll
        for (int i = t; i < BM * (BK / 4); i += 256) {     // 1024 16B chunks
            int r  = i >> 3;
            int c4 = i & 7;
            int grow = min(row0 + r, M - 1);               // clamp; rows >= M never stored
            cp_async16(sA[buf] + (uint32_t)(r * BKP + c4 * 4) * 4,
                       A + (size_t)grow * K + (size_t)it * BK + c4 * 4);
        }
        #pragma unroll
        for (int i = t; i < BK * (BN / 4); i += 256) {
            int k  = i >> 5;
            int n4 = i & 31;
            cp_async16(sB[buf] + (uint32_t)(k * BNP + n4 * 4) * 4,
                       W + (size_t)(it * BK + k) * NOUT + n0 + n4 * 4);
        }
    };

    float acc[2][8][4];
    #pragma unroll
    for (int m = 0; m < 2; m++)
        #pragma unroll
        for (int j = 0; j < 8; j++)
            #pragma unroll
            for (int c = 0; c < 4; c++) acc[m][j][c] = 0.0f;

    load_tile(0, 0);
    CP_COMMIT();

    for (int it = 0; it < NT; it++) {
        const int buf = it & 1;
        if (it + 1 < NT) {
            load_tile(it + 1, buf ^ 1);
            CP_COMMIT();
            CP_WAIT1();
        } else {
            CP_WAIT0();
        }
        __syncthreads();

        const float* As = Abuf[buf];
        const float* Bs = Bbuf[buf];
        #pragma unroll
        for (int kk = 0; kk < BK / 8; kk++) {
            uint32_t af[2][4];
            #pragma unroll
            for (int m = 0; m < 2; m++) {
                int r = wm0 + m * 16 + qid;
                int c = kk * 8 + rid;
                af[m][0] = f2tf32(As[r * BKP + c]);
                af[m][1] = f2tf32(As[(r + 8) * BKP + c]);
                af[m][2] = f2tf32(As[r * BKP + c + 4]);
                af[m][3] = f2tf32(As[(r + 8) * BKP + c + 4]);
            }
            uint32_t bf[8][2];
            #pragma unroll
            for (int j = 0; j < 8; j++) {
                int k = kk * 8 + rid;
                int n = wn0 + j * 8 + qid;
                bf[j][0] = f2tf32(Bs[k * BNP + n]);
                bf[j][1] = f2tf32(Bs[(k + 4) * BNP + n]);
            }
            #pragma unroll
            for (int m = 0; m < 2; m++)
                #pragma unroll
                for (int j = 0; j < 8; j++)
                    mma_16n8k8(acc[m][j], af[m], bf[j]);
        }
        __syncthreads();
    }

    #pragma unroll
    for (int m = 0; m < 2; m++) {
        int r_lo = row0 + wm0 + m * 16 + qid;
        int r_hi = r_lo + 8;
        #pragma unroll
        for (int j = 0; j < 8; j++) {
            int col = n0 + wn0 + j * 8 + 2 * rid;
            float b0 = bias[col], b1 = bias[col + 1];
            float2 lo = make_float2(acc[m][j][0] + b0, acc[m][j][1] + b1);
            float2 hi = make_float2(acc[m][j][2] + b0, acc[m][j][3] + b1);
            if (RELU) {
                lo.x = fmaxf(lo.x, 0.f); lo.y = fmaxf(lo.y, 0.f);
                hi.x = fmaxf(hi.x, 0.f); hi.y = fmaxf(hi.y, 0.f);
            }
            if (r_lo < M) *(float2*)(C + (size_t)r_lo * NOUT + col) = lo;
            if (r_hi < M) *(float2*)(C + (size_t)r_hi * NOUT + col) = hi;
        }
    }
}

// ---------------- out = LayerNorm(a + b) * g + be, one warp per row ----------------
__global__ void add_ln_kernel(size_t aOff, size_t bOff,
                              const float* __restrict__ g, const float* __restrict__ be,
                              size_t oOff, int M)
{
    int w = (blockIdx.x * blockDim.x + threadIdx.x) >> 5;
    if (w >= M) return;
    int lane = threadIdx.x & 31;
    float4 a = ((const float4*)(d_scratch + aOff + (size_t)w * 128))[lane];
    float4 b = ((const float4*)(d_scratch + bOff + (size_t)w * 128))[lane];
    float v0 = a.x + b.x, v1 = a.y + b.y, v2 = a.z + b.z, v3 = a.w + b.w;

    float s = v0 + v1 + v2 + v3;
    #pragma unroll
    for (int o = 16; o; o >>= 1) s += __shfl_xor_sync(0xffffffffu, s, o);
    float mean = s * (1.0f / 128.0f);
    float d0 = v0 - mean, d1 = v1 - mean, d2 = v2 - mean, d3 = v3 - mean;
    float sq = d0 * d0 + d1 * d1 + d2 * d2 + d3 * d3;
    #pragma unroll
    for (int o = 16; o; o >>= 1) sq += __shfl_xor_sync(0xffffffffu, sq, o);
    float inv = rsqrtf(sq * (1.0f / 128.0f) + 1e-5f);

    float4 gg = ((const float4*)g)[lane];
    float4 bb = ((const float4*)be)[lane];
    float4 o4 = make_float4(d0 * inv * gg.x + bb.x, d1 * inv * gg.y + bb.y,
                            d2 * inv * gg.z + bb.z, d3 * inv * gg.w + bb.w);
    ((float4*)(d_scratch + oOff + (size_t)w * 128))[lane] = o4;
}

// ---------------- column sums of x into acc ----------------
__global__ void colsum_kernel(int M) {
    int d = threadIdx.x;   // 0..127
    const float* x = d_scratch + OFF_X;
    float s = 0.0f;
    for (int r = blockIdx.x; r < M; r += gridDim.x)
        s += x[(size_t)r * 128 + d];
    atomicAdd(&d_scratch[OFF_ACC + d], s);
}

// ---------------- MLP readout: mean -> 64 -> 32 -> 10 ----------------
__global__ void readout_kernel(const float* __restrict__ mW0, const float* __restrict__ mb0,
                               const float* __restrict__ mW1, const float* __restrict__ mb1,
                               const float* __restrict__ mW2, const float* __restrict__ mb2,
                               float* __restrict__ out)
{
    __shared__ float mean[128], h0[64], h1[32];
    int t = threadIdx.x;
    mean[t] = d_scratch[OFF_ACC + t] * (1.0f / (float)NN);
    __syncthreads();
    if (t < 64) {
        float s = mb0[t];
        #pragma unroll 4
        for (int i = 0; i < 128; i++) s += mean[i] * mW0[i * 64 + t];
        h0[t] = fmaxf(s, 0.0f);
    }
    __syncthreads();
    if (t < 32) {
        float s = mb1[t];
        #pragma unroll 4
        for (int i = 0; i < 64; i++) s += h0[i] * mW1[i * 32 + t];
        h1[t] = fmaxf(s, 0.0f);
    }
    __syncthreads();
    if (t < 10) {
        float s = mb2[t];
        #pragma unroll
        for (int i = 0; i < 32; i++) s += h1[i] * mW2[i * 10 + t];
        out[t] = s;
    }
}

// ---------------- host orchestration ----------------
extern "C" void kernel_launch(void* const* d_in, const int* in_sizes, int n_in,
                              void* d_out, int out_size)
{
    const int*   x_idx = (const int*)d_in[0];
    const int*   ei    = (const int*)d_in[1];
    const float* emb   = (const float*)d_in[2];
    const float* Wq  = (const float*)d_in[3];
    const float* bq  = (const float*)d_in[4];
    const float* Wk  = (const float*)d_in[5];
    const float* bk  = (const float*)d_in[6];
    const float* Wv  = (const float*)d_in[7];
    const float* bv  = (const float*)d_in[8];
    const float* Wo  = (const float*)d_in[9];
    const float* bo  = (const float*)d_in[10];
    const float* g1  = (const float*)d_in[11];
    const float* be1 = (const float*)d_in[12];
    const float* Wf1 = (const float*)d_in[13];
    const float* bf1 = (const float*)d_in[14];
    const float* Wf2 = (const float*)d_in[15];
    const float* bf2 = (const float*)d_in[16];
    const float* g2  = (const float*)d_in[17];
    const float* be2 = (const float*)d_in[18];
    const float* mW0 = (const float*)d_in[19];
    const float* mb0 = (const float*)d_in[20];
    const float* mW1 = (const float*)d_in[21];
    const float* mb1 = (const float*)d_in[22];
    const float* mW2 = (const float*)d_in[23];
    const float* mb2 = (const float*)d_in[24];

    const int M = NN;
    const dim3 g128((M + 127) / 128, 1);            // 391 x 1
    const dim3 g256((M + 127) / 128, 2);            // 391 x 2 (NOUT=256)
    const int elem_grid = (NN * DD + 255) / 256;    // 25000
    const int edge_grid = (EE + 255) / 256;         // 3125
    const int node_grid = (NN + 255) / 256;         // 196
    const int warp_grid = (NN * 32 + 255) / 256;    // 6250

    // dynamic smem: GEMM = 2*(128*36 + 32*132)*4 = 70,656 B ; csr_scan = NN*4 = 200,000 B
    const int GEMM_SMEM = 2 * (128 * 36 + 32 * 132) * 4;
    const int CSR_SMEM  = NN * 4;
    cudaFuncSetAttribute(gemm_mma<128, 128, false>, cudaFuncAttributeMaxDynamicSharedMemorySize, GEMM_SMEM);
    cudaFuncSetAttribute(gemm_mma<128, 256, true >, cudaFuncAttributeMaxDynamicSharedMemorySize, GEMM_SMEM);
    cudaFuncSetAttribute(gemm_mma<256, 128, false>, cudaFuncAttributeMaxDynamicSharedMemorySize, GEMM_SMEM);
    cudaFuncSetAttribute(csr_scan, cudaFuncAttributeMaxDynamicSharedMemorySize, CSR_SMEM);

    embed_kernel<<<elem_grid, 256>>>(x_idx, emb);

    // CSR build (edge_index invariant across layers)
    csr_zero_counts<<<node_grid, 256>>>();
    csr_hist<<<edge_grid, 256>>>(ei);
    csr_scan<<<1, 1024, CSR_SMEM>>>();
    csr_scatter<<<edge_grid, 256>>>(ei);

    for (int l = 0; l < LL; l++) {
        const float* wq = Wq + (size_t)l * DD * DD;
        const float* wk = Wk + (size_t)l * DD * DD;
        const float* wv = Wv + (size_t)l * DD * DD;
        const float* wo = Wo + (size_t)l * DD * DD;

        gemm_mma<128, 128, false><<<g128, 256, GEMM_SMEM>>>(OFF_X, wq, bq + l * DD, OFF_Q, M);
        gemm_mma<128, 128, false><<<g128, 256, GEMM_SMEM>>>(OFF_X, wk, bk + l * DD, OFF_K, M);
        gemm_mma<128, 128, false><<<g128, 256, GEMM_SMEM>>>(OFF_X, wv, bv + l * DD, OFF_V, M);

        attn_gather_kernel<<<warp_grid, 256>>>();

        gemm_mma<128, 128, false><<<g128, 256, GEMM_SMEM>>>(OFF_ATT, wo, bo + l * DD, OFF_Y, M);
        add_ln_kernel<<<(M + 7) / 8, 256>>>(OFF_X, OFF_Y, g1 + l * DD, be1 + l * DD, OFF_X1, M);

        gemm_mma<128, 256, true ><<<g256, 256, GEMM_SMEM>>>(OFF_Y, Wf1 + (size_t)l * DD * 2 * DD,
                                                            bf1 + l * 2 * DD, OFF_T, M);
        gemm_mma<256, 128, false><<<g128, 256, GEMM_SMEM>>>(OFF_T, Wf2 + (size_t)l * 2 * DD * DD,
                                                            bf2 + l * DD, OFF_Y2, M);
        add_ln_kernel<<<(M + 7) / 8, 256>>>(OFF_X1, OFF_Y2, g2 + l * DD, be2 + l * DD, OFF_X, M);
    }

    zero_kernel<<<1, 256>>>(OFF_ACC, 128);
    colsum_kernel<<<256, 128>>>(M);
    readout_kernel<<<1, 128>>>(mW0, mb0, mW1, mb1, mW2, mb2, (float*)d_out);
}